// round 1
// baseline (speedup 1.0000x reference)
#include <cuda_runtime.h>
#include <cuda_bf16.h>
#include <cstdint>

// Problem constants
#define BB 8
#define CC 512
#define NN 4096
#define DD 64

// ---------------- scratch (device globals; no allocations allowed) ----------
__device__ __nv_bfloat16 g_attn[(long)BB * NN * NN];     // 256 MB, unnormalized exp(qk)
__device__ __nv_bfloat16 g_xbf[(long)BB * CC * NN];      // 32 MB
__device__ __nv_bfloat16 g_v[(long)BB * CC * NN];        // 32 MB
__device__ __nv_bfloat16 g_Wvbf[CC * CC];                // 512 KB
__device__ float g_q[(long)BB * DD * NN];                // 8 MB  [b][d][n]
__device__ float g_k[(long)BB * DD * NN];                // 8 MB  [b][d][n]
__device__ float g_colpart[(long)BB * 32 * NN];          // per-row-tile column partial sums
__device__ float g_colsum[BB * NN];                      // gamma / colsum

// ---------------- helpers ----------------------------------------------------
__device__ __forceinline__ float fast_exp(float x) {
    // exp(x) = 2^(x*log2e); 2^f via degree-6 Taylor on [0,1), rel err ~5e-6
    float t = x * 1.4426950408889634f;
    float fi = floorf(t);
    float f = t - fi;
    float p = 1.5403530e-4f;
    p = fmaf(p, f, 1.3333558e-3f);
    p = fmaf(p, f, 9.6181291e-3f);
    p = fmaf(p, f, 5.5504109e-2f);
    p = fmaf(p, f, 2.4022651e-1f);
    p = fmaf(p, f, 6.9314718e-1f);
    p = fmaf(p, f, 1.0f);
    int ei = (int)fi;
    float sc = __int_as_float((ei + 127) << 23);
    return p * sc;
}

__device__ __forceinline__ void ldsm_x4(unsigned r[4], uint32_t a) {
    asm volatile("ldmatrix.sync.aligned.m8n8.x4.shared.b16 {%0,%1,%2,%3}, [%4];"
                 : "=r"(r[0]), "=r"(r[1]), "=r"(r[2]), "=r"(r[3]) : "r"(a));
}
__device__ __forceinline__ void ldsm_x4t(unsigned r[4], uint32_t a) {
    asm volatile("ldmatrix.sync.aligned.m8n8.x4.trans.shared.b16 {%0,%1,%2,%3}, [%4];"
                 : "=r"(r[0]), "=r"(r[1]), "=r"(r[2]), "=r"(r[3]) : "r"(a));
}
__device__ __forceinline__ void mma_bf16(float c[4], const unsigned a[4], const unsigned b2[2]) {
    asm volatile("mma.sync.aligned.m16n8k16.row.col.f32.bf16.bf16.f32 "
                 "{%0,%1,%2,%3},{%4,%5,%6,%7},{%8,%9},{%0,%1,%2,%3};"
                 : "+f"(c[0]), "+f"(c[1]), "+f"(c[2]), "+f"(c[3])
                 : "r"(a[0]), "r"(a[1]), "r"(a[2]), "r"(a[3]), "r"(b2[0]), "r"(b2[1]));
}

// ---------------- converts ---------------------------------------------------
__global__ void cvt_x_kernel(const float* __restrict__ x) {
    long i = ((long)blockIdx.x * blockDim.x + threadIdx.x) * 4;
    float4 v = *(const float4*)(x + i);
    *(__nv_bfloat162*)(g_xbf + i)     = __floats2bfloat162_rn(v.x, v.y);
    *(__nv_bfloat162*)(g_xbf + i + 2) = __floats2bfloat162_rn(v.z, v.w);
}
__global__ void cvt_wv_kernel(const float* __restrict__ w) {
    long i = ((long)blockIdx.x * blockDim.x + threadIdx.x) * 4;
    float4 v = *(const float4*)(w + i);
    *(__nv_bfloat162*)(g_Wvbf + i)     = __floats2bfloat162_rn(v.x, v.y);
    *(__nv_bfloat162*)(g_Wvbf + i + 2) = __floats2bfloat162_rn(v.z, v.w);
}

// ---------------- q/k projection, fp32 (precision-critical) ------------------
// out rows dd: 0..63 -> q via Wq, 64..127 -> k via Wk.  GEMM M=128,K=512,Ntile=64
__global__ __launch_bounds__(128)
void qkproj_kernel(const float* __restrict__ x, const float* __restrict__ Wq,
                   const float* __restrict__ Wk) {
    __shared__ float As[16 * 132];  // [kk][dd]
    __shared__ float Bs[16 * 68];   // [kk][nn]
    int b = blockIdx.y;
    int nbase = blockIdx.x * 64;
    int tid = threadIdx.x;
    int tr = tid >> 3, tc = tid & 7;
    float acc[8][8];
#pragma unroll
    for (int i = 0; i < 8; i++)
#pragma unroll
        for (int j = 0; j < 8; j++) acc[i][j] = 0.f;

    int l_kk = tid & 15, l_dd0 = tid >> 4;   // A loader
    int l_nn = tid & 63, l_kk0 = tid >> 6;   // B loader
    const float* xb = x + (long)b * CC * NN;

    for (int c0 = 0; c0 < 512; c0 += 16) {
#pragma unroll
        for (int i = 0; i < 16; i++) {
            int dd = l_dd0 + i * 8;
            const float* W = (dd < 64) ? (Wq + dd * 512) : (Wk + (dd - 64) * 512);
            As[l_kk * 132 + dd] = W[c0 + l_kk];
        }
#pragma unroll
        for (int i = 0; i < 8; i++) {
            int kk = l_kk0 + i * 2;
            Bs[kk * 68 + l_nn] = xb[(long)(c0 + kk) * NN + nbase + l_nn];
        }
        __syncthreads();
#pragma unroll
        for (int kk = 0; kk < 16; kk++) {
            float4 a0 = *(const float4*)&As[kk * 132 + tr * 8];
            float4 a1 = *(const float4*)&As[kk * 132 + tr * 8 + 4];
            float4 b0 = *(const float4*)&Bs[kk * 68 + tc * 8];
            float4 b1 = *(const float4*)&Bs[kk * 68 + tc * 8 + 4];
            float av[8] = {a0.x, a0.y, a0.z, a0.w, a1.x, a1.y, a1.z, a1.w};
            float bv[8] = {b0.x, b0.y, b0.z, b0.w, b1.x, b1.y, b1.z, b1.w};
#pragma unroll
            for (int i = 0; i < 8; i++)
#pragma unroll
                for (int j = 0; j < 8; j++) acc[i][j] = fmaf(av[i], bv[j], acc[i][j]);
        }
        __syncthreads();
    }
#pragma unroll
    for (int i = 0; i < 8; i++) {
        int dd = tr * 8 + i;
        float* dst = (dd < 64) ? (g_q + ((long)b * DD + dd) * NN)
                               : (g_k + ((long)b * DD + dd - 64) * NN);
        float4 o0 = {acc[i][0], acc[i][1], acc[i][2], acc[i][3]};
        float4 o1 = {acc[i][4], acc[i][5], acc[i][6], acc[i][7]};
        *(float4*)(dst + nbase + tc * 8)     = o0;
        *(float4*)(dst + nbase + tc * 8 + 4) = o1;
    }
}

// ---------------- qk GEMM (fp32, K=64) fused with exp + column partials ------
// attn[n][m] = exp( sum_d q[d][n]*k[d][m] )  (unnormalized), colpart = per-tile col sums
__global__ __launch_bounds__(256)
void qk_exp_kernel() {
    __shared__ float As[32 * 132];  // [kk][n-local]
    __shared__ float Bs[32 * 132];  // [kk][m-local]
    int b = blockIdx.z;
    int rowbase = blockIdx.y * 128;  // n
    int colbase = blockIdx.x * 128;  // m
    int tid = threadIdx.x;
    int tr = tid >> 4, tc = tid & 15;
    float acc[8][8];
#pragma unroll
    for (int i = 0; i < 8; i++)
#pragma unroll
        for (int j = 0; j < 8; j++) acc[i][j] = 0.f;

    const float* qb = g_q + (long)b * DD * NN;
    const float* kb = g_k + (long)b * DD * NN;
    int lcol = tid & 127, lrow = tid >> 7;

    for (int k0 = 0; k0 < 64; k0 += 32) {
#pragma unroll
        for (int i = 0; i < 16; i++) {
            int kk = lrow + i * 2;
            As[kk * 132 + lcol] = qb[(long)(k0 + kk) * NN + rowbase + lcol];
            Bs[kk * 132 + lcol] = kb[(long)(k0 + kk) * NN + colbase + lcol];
        }
        __syncthreads();
#pragma unroll
        for (int kk = 0; kk < 32; kk++) {
            float4 a0 = *(const float4*)&As[kk * 132 + tr * 8];
            float4 a1 = *(const float4*)&As[kk * 132 + tr * 8 + 4];
            float4 b0 = *(const float4*)&Bs[kk * 132 + tc * 8];
            float4 b1 = *(const float4*)&Bs[kk * 132 + tc * 8 + 4];
            float av[8] = {a0.x, a0.y, a0.z, a0.w, a1.x, a1.y, a1.z, a1.w};
            float bv[8] = {b0.x, b0.y, b0.z, b0.w, b1.x, b1.y, b1.z, b1.w};
#pragma unroll
            for (int i = 0; i < 8; i++)
#pragma unroll
                for (int j = 0; j < 8; j++) acc[i][j] = fmaf(av[i], bv[j], acc[i][j]);
        }
        __syncthreads();
    }

    float colp[8];
#pragma unroll
    for (int j = 0; j < 8; j++) colp[j] = 0.f;
    __nv_bfloat16* ab = g_attn + ((long)b << 24);
#pragma unroll
    for (int i = 0; i < 8; i++) {
        __nv_bfloat16 row8[8];
#pragma unroll
        for (int j = 0; j < 8; j++) {
            float e = fast_exp(acc[i][j]);
            colp[j] += e;
            row8[j] = __float2bfloat16(e);
        }
        long n = rowbase + tr * 8 + i;
        *(uint4*)(ab + n * NN + colbase + tc * 8) = *(uint4*)row8;
    }
    // deterministic tile-level column reduction via shared (reuse As)
#pragma unroll
    for (int j = 0; j < 8; j++) As[tr * 128 + tc * 8 + j] = colp[j];
    __syncthreads();
    if (tid < 128) {
        float s = 0.f;
#pragma unroll
        for (int r = 0; r < 16; r++) s += As[r * 128 + tid];
        g_colpart[((long)b * 32 + blockIdx.y) * NN + colbase + tid] = s;
    }
}

// ---------------- column sum finalize: gamma / sum ---------------------------
__global__ void rsum_kernel(const float* __restrict__ gamma) {
    int i = blockIdx.x * 256 + threadIdx.x;  // 0..32767
    int b = i >> 12, col = i & 4095;
    const float* p = g_colpart + (long)b * 32 * NN + col;
    float s = 0.f;
#pragma unroll
    for (int t = 0; t < 32; t++) s += p[(long)t * NN];
    g_colsum[i] = gamma[0] / s;
}

// ---------------- bf16 tensor-core GEMM (v-proj and PV) ----------------------
// C[128x128] tile; 8 warps (4 M x 2 N); m16n8k16; A row-major, B row-major.
// PV=false: v = Wv @ xbf (K=512), store bf16
// PV=true : out = (v @ attn) * (gamma/colsum[m]) + x (K=4096), store fp32
template <int KDIM, bool PV>
__global__ __launch_bounds__(256, 2)
void mma_gemm_kernel(float* __restrict__ Out, const float* __restrict__ Xres) {
    __shared__ __align__(16) __nv_bfloat16 As[128 * 40];
    __shared__ __align__(16) __nv_bfloat16 Bs[32 * 136];
    int b = blockIdx.z;
    const __nv_bfloat16* A = PV ? (g_v + (long)b * CC * NN) : g_Wvbf;
    const __nv_bfloat16* Bm = PV ? (g_attn + ((long)b << 24)) : (g_xbf + (long)b * CC * NN);
    int mbase = blockIdx.y * 128, nbase = blockIdx.x * 128;
    int tid = threadIdx.x, lane = tid & 31, warp = tid >> 5;
    int wm = warp & 3, wn = warp >> 2;

    float acc[2][8][4];
#pragma unroll
    for (int t = 0; t < 2; t++)
#pragma unroll
        for (int j = 0; j < 8; j++)
#pragma unroll
            for (int e = 0; e < 4; e++) acc[t][j][e] = 0.f;

    int a_row = tid >> 2, a_kcol = (tid & 3) * 8;
    int b_n = (tid & 15) * 8, b_k = tid >> 4;
    uint32_t as_base = (uint32_t)__cvta_generic_to_shared(As);
    uint32_t bs_base = (uint32_t)__cvta_generic_to_shared(Bs);
    uint32_t a_addr = as_base + (uint32_t)(((wm * 32 + (lane & 15)) * 40 + (lane >> 4) * 8) * 2);
    uint32_t b_addr = bs_base + (uint32_t)(((lane & 15) * 136 + wn * 64 + (lane >> 4) * 8) * 2);

    for (int k0 = 0; k0 < KDIM; k0 += 32) {
#pragma unroll
        for (int p = 0; p < 2; p++) {
            uint4 v = *(const uint4*)(A + (long)(mbase + a_row + p * 64) * KDIM + k0 + a_kcol);
            *(uint4*)(&As[(a_row + p * 64) * 40 + a_kcol]) = v;
        }
#pragma unroll
        for (int p = 0; p < 2; p++) {
            uint4 v = *(const uint4*)(Bm + (long)(k0 + b_k + p * 16) * NN + nbase + b_n);
            *(uint4*)(&Bs[(b_k + p * 16) * 136 + b_n]) = v;
        }
        __syncthreads();
#pragma unroll
        for (int ks = 0; ks < 2; ks++) {
            unsigned af[2][4];
            ldsm_x4(af[0], a_addr + ks * 32);
            ldsm_x4(af[1], a_addr + 1280 + ks * 32);
#pragma unroll
            for (int jp = 0; jp < 4; jp++) {
                unsigned bf[4];
                ldsm_x4t(bf, b_addr + jp * 32 + ks * 4352);
                mma_bf16(acc[0][2 * jp],     af[0], bf);
                mma_bf16(acc[0][2 * jp + 1], af[0], bf + 2);
                mma_bf16(acc[1][2 * jp],     af[1], bf);
                mma_bf16(acc[1][2 * jp + 1], af[1], bf + 2);
            }
        }
        __syncthreads();
    }

    int row0 = mbase + wm * 32 + (lane >> 2);
    int col0 = nbase + wn * 64 + (lane & 3) * 2;
    if (!PV) {
        __nv_bfloat16* Vb = g_v + (long)b * CC * NN;
#pragma unroll
        for (int t = 0; t < 2; t++)
#pragma unroll
            for (int j = 0; j < 8; j++) {
                int r = row0 + t * 16, c = col0 + j * 8;
                *(__nv_bfloat162*)(Vb + (long)r * NN + c) =
                    __floats2bfloat162_rn(acc[t][j][0], acc[t][j][1]);
                *(__nv_bfloat162*)(Vb + (long)(r + 8) * NN + c) =
                    __floats2bfloat162_rn(acc[t][j][2], acc[t][j][3]);
            }
    } else {
        float* Ob = Out + (long)b * CC * NN;
        const float* Xb = Xres + (long)b * CC * NN;
        const float* rs = g_colsum + b * NN;
#pragma unroll
        for (int j = 0; j < 8; j++) {
            int c = col0 + j * 8;
            float r0 = rs[c], r1 = rs[c + 1];
#pragma unroll
            for (int t = 0; t < 2; t++) {
                int r = row0 + t * 16;
                float2 x0 = *(const float2*)(Xb + (long)r * NN + c);
                float2 o0 = {fmaf(acc[t][j][0], r0, x0.x), fmaf(acc[t][j][1], r1, x0.y)};
                *(float2*)(Ob + (long)r * NN + c) = o0;
                float2 x1 = *(const float2*)(Xb + (long)(r + 8) * NN + c);
                float2 o1 = {fmaf(acc[t][j][2], r0, x1.x), fmaf(acc[t][j][3], r1, x1.y)};
                *(float2*)(Ob + (long)(r + 8) * NN + c) = o1;
            }
        }
    }
}

// ---------------- launch -----------------------------------------------------
extern "C" void kernel_launch(void* const* d_in, const int* in_sizes, int n_in,
                              void* d_out, int out_size) {
    const float* x     = (const float*)d_in[0];
    const float* Wq    = (const float*)d_in[1];
    const float* Wk    = (const float*)d_in[2];
    const float* Wv    = (const float*)d_in[3];
    const float* gamma = (const float*)d_in[4];
    float* out = (float*)d_out;

    cvt_x_kernel<<<16384, 256>>>(x);            // 16.7M elems, 4/thread
    cvt_wv_kernel<<<256, 256>>>(Wv);            // 262144 elems
    qkproj_kernel<<<dim3(64, 8), 128>>>(x, Wq, Wk);
    qk_exp_kernel<<<dim3(32, 32, 8), 256>>>();
    rsum_kernel<<<128, 256>>>(gamma);
    mma_gemm_kernel<512, false><<<dim3(32, 4, 8), 256>>>(nullptr, nullptr);   // v-proj
    mma_gemm_kernel<4096, true><<<dim3(32, 4, 8), 256>>>(out, x);             // PV + epilogue
}

// round 2
// speedup vs baseline: 2.1596x; 2.1596x over previous
#include <cuda_runtime.h>
#include <cuda_bf16.h>
#include <cstdint>

// Problem constants
#define BB 8
#define CC 512
#define NN 4096
#define DD 64

// ---------------- scratch (device globals; no allocations allowed) ----------
__device__ __nv_bfloat16 g_attn[(long)BB * NN * NN];     // 256 MB, unnormalized exp(qk)
__device__ __nv_bfloat16 g_xbf[(long)BB * CC * NN];      // 32 MB
__device__ __nv_bfloat16 g_v[(long)BB * CC * NN];        // 32 MB
__device__ __nv_bfloat16 g_Wvbf[CC * CC];                // 512 KB
__device__ float g_q[(long)BB * DD * NN];                // 8 MB  [b][d][n]
__device__ float g_k[(long)BB * DD * NN];                // 8 MB  [b][d][n]
__device__ __nv_bfloat16 g_q2t[(long)BB * NN * 128];     // 8 MB  [b][n][d: hi0-63|lo64-127]
__device__ __nv_bfloat16 g_k2[(long)BB * 128 * NN];      // 8 MB  [b][d hi|lo][m]
__device__ float g_colpart[(long)BB * 32 * NN];          // per-row-tile column partial sums
__device__ float g_colsum[BB * NN];                      // gamma / colsum

// ---------------- helpers ----------------------------------------------------
__device__ __forceinline__ float fast_exp(float x) {
    float t = x * 1.4426950408889634f;
    float fi = floorf(t);
    float f = t - fi;
    float p = 1.5403530e-4f;
    p = fmaf(p, f, 1.3333558e-3f);
    p = fmaf(p, f, 9.6181291e-3f);
    p = fmaf(p, f, 5.5504109e-2f);
    p = fmaf(p, f, 2.4022651e-1f);
    p = fmaf(p, f, 6.9314718e-1f);
    p = fmaf(p, f, 1.0f);
    int ei = (int)fi;
    float sc = __int_as_float((ei + 127) << 23);
    return p * sc;
}

__device__ __forceinline__ void ldsm_x4(unsigned r[4], uint32_t a) {
    asm volatile("ldmatrix.sync.aligned.m8n8.x4.shared.b16 {%0,%1,%2,%3}, [%4];"
                 : "=r"(r[0]), "=r"(r[1]), "=r"(r[2]), "=r"(r[3]) : "r"(a));
}
__device__ __forceinline__ void ldsm_x4t(unsigned r[4], uint32_t a) {
    asm volatile("ldmatrix.sync.aligned.m8n8.x4.trans.shared.b16 {%0,%1,%2,%3}, [%4];"
                 : "=r"(r[0]), "=r"(r[1]), "=r"(r[2]), "=r"(r[3]) : "r"(a));
}
__device__ __forceinline__ void mma_bf16(float c[4], const unsigned a[4], const unsigned b2[2]) {
    asm volatile("mma.sync.aligned.m16n8k16.row.col.f32.bf16.bf16.f32 "
                 "{%0,%1,%2,%3},{%4,%5,%6,%7},{%8,%9},{%0,%1,%2,%3};"
                 : "+f"(c[0]), "+f"(c[1]), "+f"(c[2]), "+f"(c[3])
                 : "r"(a[0]), "r"(a[1]), "r"(a[2]), "r"(a[3]), "r"(b2[0]), "r"(b2[1]));
}
__device__ __forceinline__ void cp16(uint32_t s, const void* g) {
    asm volatile("cp.async.cg.shared.global [%0], [%1], 16;" :: "r"(s), "l"(g));
}

// ---------------- converts ---------------------------------------------------
__global__ void cvt_x_kernel(const float* __restrict__ x) {
    long i = ((long)blockIdx.x * blockDim.x + threadIdx.x) * 4;
    float4 v = *(const float4*)(x + i);
    *(__nv_bfloat162*)(g_xbf + i)     = __floats2bfloat162_rn(v.x, v.y);
    *(__nv_bfloat162*)(g_xbf + i + 2) = __floats2bfloat162_rn(v.z, v.w);
}
__global__ void cvt_wv_kernel(const float* __restrict__ w) {
    long i = ((long)blockIdx.x * blockDim.x + threadIdx.x) * 4;
    float4 v = *(const float4*)(w + i);
    *(__nv_bfloat162*)(g_Wvbf + i)     = __floats2bfloat162_rn(v.x, v.y);
    *(__nv_bfloat162*)(g_Wvbf + i + 2) = __floats2bfloat162_rn(v.z, v.w);
}

// ---------------- q/k projection, fp32 (precision-critical) ------------------
__global__ __launch_bounds__(128)
void qkproj_kernel(const float* __restrict__ x, const float* __restrict__ Wq,
                   const float* __restrict__ Wk) {
    __shared__ float As[16 * 132];
    __shared__ float Bs[16 * 68];
    int b = blockIdx.y;
    int nbase = blockIdx.x * 64;
    int tid = threadIdx.x;
    int tr = tid >> 3, tc = tid & 7;
    float acc[8][8];
#pragma unroll
    for (int i = 0; i < 8; i++)
#pragma unroll
        for (int j = 0; j < 8; j++) acc[i][j] = 0.f;

    int l_kk = tid & 15, l_dd0 = tid >> 4;
    int l_nn = tid & 63, l_kk0 = tid >> 6;
    const float* xb = x + (long)b * CC * NN;

    for (int c0 = 0; c0 < 512; c0 += 16) {
#pragma unroll
        for (int i = 0; i < 16; i++) {
            int dd = l_dd0 + i * 8;
            const float* W = (dd < 64) ? (Wq + dd * 512) : (Wk + (dd - 64) * 512);
            As[l_kk * 132 + dd] = W[c0 + l_kk];
        }
#pragma unroll
        for (int i = 0; i < 8; i++) {
            int kk = l_kk0 + i * 2;
            Bs[kk * 68 + l_nn] = xb[(long)(c0 + kk) * NN + nbase + l_nn];
        }
        __syncthreads();
#pragma unroll
        for (int kk = 0; kk < 16; kk++) {
            float4 a0 = *(const float4*)&As[kk * 132 + tr * 8];
            float4 a1 = *(const float4*)&As[kk * 132 + tr * 8 + 4];
            float4 b0 = *(const float4*)&Bs[kk * 68 + tc * 8];
            float4 b1 = *(const float4*)&Bs[kk * 68 + tc * 8 + 4];
            float av[8] = {a0.x, a0.y, a0.z, a0.w, a1.x, a1.y, a1.z, a1.w};
            float bv[8] = {b0.x, b0.y, b0.z, b0.w, b1.x, b1.y, b1.z, b1.w};
#pragma unroll
            for (int i = 0; i < 8; i++)
#pragma unroll
                for (int j = 0; j < 8; j++) acc[i][j] = fmaf(av[i], bv[j], acc[i][j]);
        }
        __syncthreads();
    }
#pragma unroll
    for (int i = 0; i < 8; i++) {
        int dd = tr * 8 + i;
        float* dst = (dd < 64) ? (g_q + ((long)b * DD + dd) * NN)
                               : (g_k + ((long)b * DD + dd - 64) * NN);
        float4 o0 = {acc[i][0], acc[i][1], acc[i][2], acc[i][3]};
        float4 o1 = {acc[i][4], acc[i][5], acc[i][6], acc[i][7]};
        *(float4*)(dst + nbase + tc * 8)     = o0;
        *(float4*)(dst + nbase + tc * 8 + 4) = o1;
    }
}

// ---------------- split fp32 -> (hi, lo) bf16 --------------------------------
// k2[b][d][m]: d<64 = hi, d>=64 = lo. Elementwise, coalesced.
__global__ void split_k_kernel() {
    long i = ((long)blockIdx.x * 256 + threadIdx.x) * 4;  // over B*64*4096 floats
    float4 v = *(const float4*)(g_k + i);
    float h0 = __bfloat162float(__float2bfloat16(v.x));
    float h1 = __bfloat162float(__float2bfloat16(v.y));
    float h2 = __bfloat162float(__float2bfloat16(v.z));
    float h3 = __bfloat162float(__float2bfloat16(v.w));
    long b = i / (64L * 4096);
    long r = i - b * (64L * 4096);
    __nv_bfloat16* dst = g_k2 + b * (128L * 4096);
    *(__nv_bfloat162*)(dst + r)     = __floats2bfloat162_rn(h0, h1);
    *(__nv_bfloat162*)(dst + r + 2) = __floats2bfloat162_rn(h2, h3);
    __nv_bfloat16* dl = dst + 64L * 4096;
    *(__nv_bfloat162*)(dl + r)     = __floats2bfloat162_rn(v.x - h0, v.y - h1);
    *(__nv_bfloat162*)(dl + r + 2) = __floats2bfloat162_rn(v.z - h2, v.w - h3);
}

// q2t[b][n][0..63]=hi, [64..127]=lo  (transpose of g_q [d][n])
__global__ __launch_bounds__(256) void split_q_kernel() {
    __shared__ __nv_bfloat16 shi[64 * 65];
    __shared__ __nv_bfloat16 slo[64 * 65];
    int b = blockIdx.y;
    int n0 = blockIdx.x * 64;
    int t = threadIdx.x;
    const float* src = g_q + (long)b * 64 * NN;
#pragma unroll
    for (int i = 0; i < 16; i++) {
        int idx = i * 256 + t;
        int d = idx >> 6, n = idx & 63;
        float v = src[(long)d * NN + n0 + n];
        __nv_bfloat16 h = __float2bfloat16(v);
        shi[d * 65 + n] = h;
        slo[d * 65 + n] = __float2bfloat16(v - __bfloat162float(h));
    }
    __syncthreads();
    __nv_bfloat16* dst = g_q2t + (long)b * NN * 128;
#pragma unroll
    for (int i = 0; i < 8; i++) {
        int idx = i * 256 + t;          // 0..2047
        int n = idx >> 5, j = idx & 31; // 32 uint2 per output row
        const __nv_bfloat16* sarr = (j < 16) ? shi : slo;
        int d0 = (j & 15) * 4;
        __nv_bfloat16 tmp[4];
#pragma unroll
        for (int r = 0; r < 4; r++) tmp[r] = sarr[(d0 + r) * 65 + n];
        int dc = (j < 16) ? d0 : (64 + d0);
        *(uint2*)(dst + (long)(n0 + n) * 128 + dc) = *(uint2*)tmp;
    }
}

// ---------------- qk via bf16 split GEMM (K=128) + exp + colpart -------------
__global__ __launch_bounds__(256, 2)
void qk_mma_kernel() {
    constexpr int KD = 128;
    constexpr int NIT = KD / 32;
    __shared__ __align__(16) __nv_bfloat16 As[2 * 128 * 40];
    __shared__ __align__(16) __nv_bfloat16 Bs[2 * 32 * 136];
    __shared__ float cred[4 * 128];
    int b = blockIdx.z;
    const __nv_bfloat16* A  = g_q2t + (long)b * NN * 128;   // [n][128]
    const __nv_bfloat16* Bm = g_k2  + (long)b * 128 * NN;   // [k][m]
    int mbase = blockIdx.y * 128;  // n (softmax axis)
    int nbase = blockIdx.x * 128;  // m
    int tid = threadIdx.x, lane = tid & 31, warp = tid >> 5;
    int wm = warp & 3, wn = warp >> 2;

    float acc[2][8][4];
#pragma unroll
    for (int t = 0; t < 2; t++)
#pragma unroll
        for (int j = 0; j < 8; j++)
#pragma unroll
            for (int e = 0; e < 4; e++) acc[t][j][e] = 0.f;

    uint32_t as0 = (uint32_t)__cvta_generic_to_shared(As);
    uint32_t bs0 = (uint32_t)__cvta_generic_to_shared(Bs);
    uint32_t a_st = ((tid >> 2) * 40 + (tid & 3) * 8) * 2;
    uint32_t b_st = ((tid >> 4) * 136 + (tid & 15) * 8) * 2;
    const long a_g0 = (long)(mbase + (tid >> 2)) * KD + (tid & 3) * 8;
    const long b_g0 = (long)(tid >> 4) * NN + nbase + (tid & 15) * 8;
    uint32_t a_off = ((wm * 32 + (lane & 15)) * 40 + (lane >> 4) * 8) * 2;
    uint32_t b_off = ((lane & 15) * 136 + wn * 64 + (lane >> 4) * 8) * 2;

#define QK_ISSUE(k0, st)                                                        \
    {                                                                           \
        uint32_t ab = as0 + (st) * 10240, bb = bs0 + (st) * 8704;               \
        cp16(ab + a_st, A + a_g0 + (k0));                                       \
        cp16(ab + a_st + 64 * 80, A + a_g0 + 64L * KD + (k0));                  \
        cp16(bb + b_st, Bm + b_g0 + (long)(k0) * NN);                           \
        cp16(bb + b_st + 16 * 272, Bm + b_g0 + (long)((k0) + 16) * NN);         \
        asm volatile("cp.async.commit_group;" ::);                              \
    }

    QK_ISSUE(0, 0);
#pragma unroll
    for (int it = 0; it < NIT; it++) {
        if (it + 1 < NIT) {
            QK_ISSUE((it + 1) * 32, (it + 1) & 1);
            asm volatile("cp.async.wait_group 1;" ::);
        } else {
            asm volatile("cp.async.wait_group 0;" ::);
        }
        __syncthreads();
        uint32_t aa = as0 + (it & 1) * 10240 + a_off;
        uint32_t bbq = bs0 + (it & 1) * 8704 + b_off;
#pragma unroll
        for (int ks = 0; ks < 2; ks++) {
            unsigned af[2][4];
            ldsm_x4(af[0], aa + ks * 32);
            ldsm_x4(af[1], aa + 1280 + ks * 32);
#pragma unroll
            for (int jp = 0; jp < 4; jp++) {
                unsigned bf[4];
                ldsm_x4t(bf, bbq + jp * 32 + ks * 4352);
                mma_bf16(acc[0][2 * jp],     af[0], bf);
                mma_bf16(acc[0][2 * jp + 1], af[0], bf + 2);
                mma_bf16(acc[1][2 * jp],     af[1], bf);
                mma_bf16(acc[1][2 * jp + 1], af[1], bf + 2);
            }
        }
        __syncthreads();
    }
#undef QK_ISSUE

    // epilogue: exp, store attn bf16, column partial sums
    __nv_bfloat16* ab = g_attn + ((long)b << 24);
    int row0 = mbase + wm * 32 + (lane >> 2);
    int col0 = nbase + wn * 64 + (lane & 3) * 2;
    float colp[8][2];
#pragma unroll
    for (int j = 0; j < 8; j++) { colp[j][0] = 0.f; colp[j][1] = 0.f; }
#pragma unroll
    for (int t = 0; t < 2; t++)
#pragma unroll
        for (int j = 0; j < 8; j++) {
            float e0 = fast_exp(acc[t][j][0]);
            float e1 = fast_exp(acc[t][j][1]);
            float e2 = fast_exp(acc[t][j][2]);
            float e3 = fast_exp(acc[t][j][3]);
            colp[j][0] += e0 + e2;
            colp[j][1] += e1 + e3;
            int r = row0 + t * 16, c = col0 + j * 8;
            *(__nv_bfloat162*)(ab + (long)r * NN + c)       = __floats2bfloat162_rn(e0, e1);
            *(__nv_bfloat162*)(ab + (long)(r + 8) * NN + c) = __floats2bfloat162_rn(e2, e3);
        }
    // reduce over the 8 lane-groups holding the same columns (bits 2..4 of lane)
#pragma unroll
    for (int off = 16; off >= 4; off >>= 1)
#pragma unroll
        for (int j = 0; j < 8; j++) {
            colp[j][0] += __shfl_xor_sync(0xffffffffu, colp[j][0], off);
            colp[j][1] += __shfl_xor_sync(0xffffffffu, colp[j][1], off);
        }
    if ((lane >> 2) == 0) {
#pragma unroll
        for (int j = 0; j < 8; j++) {
            cred[wm * 128 + wn * 64 + j * 8 + (lane & 3) * 2]     = colp[j][0];
            cred[wm * 128 + wn * 64 + j * 8 + (lane & 3) * 2 + 1] = colp[j][1];
        }
    }
    __syncthreads();
    if (tid < 128) {
        float s = cred[tid] + cred[128 + tid] + cred[256 + tid] + cred[384 + tid];
        g_colpart[((long)b * 32 + blockIdx.y) * NN + nbase + tid] = s;
    }
}

// ---------------- column sum finalize: gamma / sum ---------------------------
__global__ void rsum_kernel(const float* __restrict__ gamma) {
    int i = blockIdx.x * 256 + threadIdx.x;
    int b = i >> 12, col = i & 4095;
    const float* p = g_colpart + (long)b * 32 * NN + col;
    float s = 0.f;
#pragma unroll
    for (int t = 0; t < 32; t++) s += p[(long)t * NN];
    g_colsum[i] = gamma[0] / s;
}

// ---------------- bf16 tensor-core GEMM (v-proj and PV), cp.async pipelined --
template <int KDIM, bool PV>
__global__ __launch_bounds__(256, 2)
void mma_gemm_kernel(float* __restrict__ Out, const float* __restrict__ Xres) {
    constexpr int NIT = KDIM / 32;
    __shared__ __align__(16) __nv_bfloat16 As[2 * 128 * 40];
    __shared__ __align__(16) __nv_bfloat16 Bs[2 * 32 * 136];
    int b = blockIdx.z;
    const __nv_bfloat16* A  = PV ? (g_v + (long)b * CC * NN) : g_Wvbf;
    const __nv_bfloat16* Bm = PV ? (g_attn + ((long)b << 24)) : (g_xbf + (long)b * CC * NN);
    int mbase = blockIdx.y * 128, nbase = blockIdx.x * 128;
    int tid = threadIdx.x, lane = tid & 31, warp = tid >> 5;
    int wm = warp & 3, wn = warp >> 2;

    float acc[2][8][4];
#pragma unroll
    for (int t = 0; t < 2; t++)
#pragma unroll
        for (int j = 0; j < 8; j++)
#pragma unroll
            for (int e = 0; e < 4; e++) acc[t][j][e] = 0.f;

    uint32_t as0 = (uint32_t)__cvta_generic_to_shared(As);
    uint32_t bs0 = (uint32_t)__cvta_generic_to_shared(Bs);
    uint32_t a_st = ((tid >> 2) * 40 + (tid & 3) * 8) * 2;
    uint32_t b_st = ((tid >> 4) * 136 + (tid & 15) * 8) * 2;
    const long a_g0 = (long)(mbase + (tid >> 2)) * KDIM + (tid & 3) * 8;
    const long b_g0 = (long)(tid >> 4) * NN + nbase + (tid & 15) * 8;
    uint32_t a_off = ((wm * 32 + (lane & 15)) * 40 + (lane >> 4) * 8) * 2;
    uint32_t b_off = ((lane & 15) * 136 + wn * 64 + (lane >> 4) * 8) * 2;

#define GM_ISSUE(k0, st)                                                        \
    {                                                                           \
        uint32_t ab = as0 + (st) * 10240, bb = bs0 + (st) * 8704;               \
        cp16(ab + a_st, A + a_g0 + (k0));                                       \
        cp16(ab + a_st + 64 * 80, A + a_g0 + 64L * KDIM + (k0));                \
        cp16(bb + b_st, Bm + b_g0 + (long)(k0) * NN);                           \
        cp16(bb + b_st + 16 * 272, Bm + b_g0 + (long)((k0) + 16) * NN);         \
        asm volatile("cp.async.commit_group;" ::);                              \
    }

    GM_ISSUE(0, 0);
    for (int it = 0; it < NIT; it++) {
        if (it + 1 < NIT) {
            GM_ISSUE((it + 1) * 32, (it + 1) & 1);
            asm volatile("cp.async.wait_group 1;" ::);
        } else {
            asm volatile("cp.async.wait_group 0;" ::);
        }
        __syncthreads();
        uint32_t aa = as0 + (it & 1) * 10240 + a_off;
        uint32_t bb2 = bs0 + (it & 1) * 8704 + b_off;
#pragma unroll
        for (int ks = 0; ks < 2; ks++) {
            unsigned af[2][4];
            ldsm_x4(af[0], aa + ks * 32);
            ldsm_x4(af[1], aa + 1280 + ks * 32);
#pragma unroll
            for (int jp = 0; jp < 4; jp++) {
                unsigned bf[4];
                ldsm_x4t(bf, bb2 + jp * 32 + ks * 4352);
                mma_bf16(acc[0][2 * jp],     af[0], bf);
                mma_bf16(acc[0][2 * jp + 1], af[0], bf + 2);
                mma_bf16(acc[1][2 * jp],     af[1], bf);
                mma_bf16(acc[1][2 * jp + 1], af[1], bf + 2);
            }
        }
        __syncthreads();
    }
#undef GM_ISSUE

    int row0 = mbase + wm * 32 + (lane >> 2);
    int col0 = nbase + wn * 64 + (lane & 3) * 2;
    if (!PV) {
        __nv_bfloat16* Vb = g_v + (long)b * CC * NN;
#pragma unroll
        for (int t = 0; t < 2; t++)
#pragma unroll
            for (int j = 0; j < 8; j++) {
                int r = row0 + t * 16, c = col0 + j * 8;
                *(__nv_bfloat162*)(Vb + (long)r * NN + c) =
                    __floats2bfloat162_rn(acc[t][j][0], acc[t][j][1]);
                *(__nv_bfloat162*)(Vb + (long)(r + 8) * NN + c) =
                    __floats2bfloat162_rn(acc[t][j][2], acc[t][j][3]);
            }
    } else {
        float* Ob = Out + (long)b * CC * NN;
        const float* Xb = Xres + (long)b * CC * NN;
        const float* rs = g_colsum + b * NN;
#pragma unroll
        for (int j = 0; j < 8; j++) {
            int c = col0 + j * 8;
            float r0 = rs[c], r1 = rs[c + 1];
#pragma unroll
            for (int t = 0; t < 2; t++) {
                int r = row0 + t * 16;
                float2 x0 = *(const float2*)(Xb + (long)r * NN + c);
                float2 o0 = {fmaf(acc[t][j][0], r0, x0.x), fmaf(acc[t][j][1], r1, x0.y)};
                *(float2*)(Ob + (long)r * NN + c) = o0;
                float2 x1 = *(const float2*)(Xb + (long)(r + 8) * NN + c);
                float2 o1 = {fmaf(acc[t][j][2], r0, x1.x), fmaf(acc[t][j][3], r1, x1.y)};
                *(float2*)(Ob + (long)(r + 8) * NN + c) = o1;
            }
        }
    }
}

// ---------------- launch -----------------------------------------------------
extern "C" void kernel_launch(void* const* d_in, const int* in_sizes, int n_in,
                              void* d_out, int out_size) {
    const float* x     = (const float*)d_in[0];
    const float* Wq    = (const float*)d_in[1];
    const float* Wk    = (const float*)d_in[2];
    const float* Wv    = (const float*)d_in[3];
    const float* gamma = (const float*)d_in[4];
    float* out = (float*)d_out;

    cvt_x_kernel<<<16384, 256>>>(x);
    cvt_wv_kernel<<<256, 256>>>(Wv);
    qkproj_kernel<<<dim3(64, 8), 128>>>(x, Wq, Wk);
    split_k_kernel<<<2048, 256>>>();
    split_q_kernel<<<dim3(64, 8), 256>>>();
    qk_mma_kernel<<<dim3(32, 32, 8), 256>>>();
    rsum_kernel<<<128, 256>>>(gamma);
    mma_gemm_kernel<512, false><<<dim3(32, 4, 8), 256>>>(nullptr, nullptr);   // v-proj
    mma_gemm_kernel<4096, true><<<dim3(32, 4, 8), 256>>>(out, x);             // PV + epilogue
}

// round 3
// speedup vs baseline: 2.2054x; 1.0212x over previous
#include <cuda_runtime.h>
#include <cuda_bf16.h>
#include <cstdint>

#define BB 8
#define CC 512
#define NN 4096
#define DD 64

// ---------------- scratch ----------------------------------------------------
__device__ __nv_bfloat16 g_attn[(long)BB * NN * NN];     // 256 MB unnormalized exp(qk)
__device__ __nv_bfloat16 g_xbf[(long)BB * CC * NN];      // 32 MB  x hi
__device__ __nv_bfloat16 g_xlo[(long)BB * CC * NN];      // 32 MB  x lo
__device__ __nv_bfloat16 g_v[(long)BB * CC * NN];        // 32 MB
__device__ __nv_bfloat16 g_Wvbf[CC * CC];                // 512 KB
__device__ __nv_bfloat16 g_Wqk2[128 * 1536];             // 384 KB [d][hW|lW|hW]
__device__ float g_q[(long)BB * DD * NN];                // 8 MB [b][d][n]
__device__ float g_k[(long)BB * DD * NN];                // 8 MB [b][d][n]
__device__ __nv_bfloat16 g_q2t[(long)BB * NN * 192];     // 12 MB [b][n][hq|lq|hq]
__device__ __nv_bfloat16 g_k2[(long)BB * 192 * NN];      // 12 MB [b][hk|hk|lk][m]
__device__ float g_colpart[(long)BB * 32 * NN];
__device__ float g_colsum[BB * NN];

// ---------------- helpers ----------------------------------------------------
__device__ __forceinline__ float fast_exp(float x) {
    float t = x * 1.4426950408889634f;
    float fi = floorf(t);
    float f = t - fi;
    float p = 1.5403530e-4f;
    p = fmaf(p, f, 1.3333558e-3f);
    p = fmaf(p, f, 9.6181291e-3f);
    p = fmaf(p, f, 5.5504109e-2f);
    p = fmaf(p, f, 2.4022651e-1f);
    p = fmaf(p, f, 6.9314718e-1f);
    p = fmaf(p, f, 1.0f);
    int ei = (int)fi;
    float sc = __int_as_float((ei + 127) << 23);
    return p * sc;
}

__device__ __forceinline__ void ldsm_x4(unsigned r[4], uint32_t a) {
    asm volatile("ldmatrix.sync.aligned.m8n8.x4.shared.b16 {%0,%1,%2,%3}, [%4];"
                 : "=r"(r[0]), "=r"(r[1]), "=r"(r[2]), "=r"(r[3]) : "r"(a));
}
__device__ __forceinline__ void ldsm_x4t(unsigned r[4], uint32_t a) {
    asm volatile("ldmatrix.sync.aligned.m8n8.x4.trans.shared.b16 {%0,%1,%2,%3}, [%4];"
                 : "=r"(r[0]), "=r"(r[1]), "=r"(r[2]), "=r"(r[3]) : "r"(a));
}
__device__ __forceinline__ void mma_bf16(float c[4], const unsigned a[4], const unsigned b2[2]) {
    asm volatile("mma.sync.aligned.m16n8k16.row.col.f32.bf16.bf16.f32 "
                 "{%0,%1,%2,%3},{%4,%5,%6,%7},{%8,%9},{%0,%1,%2,%3};"
                 : "+f"(c[0]), "+f"(c[1]), "+f"(c[2]), "+f"(c[3])
                 : "r"(a[0]), "r"(a[1]), "r"(a[2]), "r"(a[3]), "r"(b2[0]), "r"(b2[1]));
}
__device__ __forceinline__ void cp16(uint32_t s, const void* g) {
    asm volatile("cp.async.cg.shared.global [%0], [%1], 16;" :: "r"(s), "l"(g));
}

// ---------------- converts ---------------------------------------------------
__global__ void cvt_x_kernel(const float* __restrict__ x) {
    long i = ((long)blockIdx.x * blockDim.x + threadIdx.x) * 4;
    float4 v = *(const float4*)(x + i);
    float h0 = __bfloat162float(__float2bfloat16(v.x));
    float h1 = __bfloat162float(__float2bfloat16(v.y));
    float h2 = __bfloat162float(__float2bfloat16(v.z));
    float h3 = __bfloat162float(__float2bfloat16(v.w));
    *(__nv_bfloat162*)(g_xbf + i)     = __floats2bfloat162_rn(h0, h1);
    *(__nv_bfloat162*)(g_xbf + i + 2) = __floats2bfloat162_rn(h2, h3);
    *(__nv_bfloat162*)(g_xlo + i)     = __floats2bfloat162_rn(v.x - h0, v.y - h1);
    *(__nv_bfloat162*)(g_xlo + i + 2) = __floats2bfloat162_rn(v.z - h2, v.w - h3);
}
__global__ void cvt_wv_kernel(const float* __restrict__ w) {
    long i = ((long)blockIdx.x * blockDim.x + threadIdx.x) * 4;
    float4 v = *(const float4*)(w + i);
    *(__nv_bfloat162*)(g_Wvbf + i)     = __floats2bfloat162_rn(v.x, v.y);
    *(__nv_bfloat162*)(g_Wvbf + i + 2) = __floats2bfloat162_rn(v.z, v.w);
}
// Wqk split: [d][0:512)=hW, [512:1024)=lW, [1024:1536)=hW (dup)
__global__ void cvt_wqk_kernel(const float* __restrict__ Wq, const float* __restrict__ Wk) {
    int i = blockIdx.x * 256 + threadIdx.x;     // 0..65535
    int d = i >> 9, c = i & 511;
    float v = (d < 64) ? Wq[d * 512 + c] : Wk[(d - 64) * 512 + c];
    __nv_bfloat16 h = __float2bfloat16(v);
    __nv_bfloat16 l = __float2bfloat16(v - __bfloat162float(h));
    g_Wqk2[d * 1536 + c] = h;
    g_Wqk2[d * 1536 + 512 + c] = l;
    g_Wqk2[d * 1536 + 1024 + c] = h;
}

// ---------------- qk projection via bf16 split GEMM (K=1536) -----------------
// D[d][n] = Wqk_split @ x_split ; rows 0..63 -> g_q, 64..127 -> g_k (fp32)
__global__ __launch_bounds__(256, 2)
void qkproj_mma_kernel() {
    constexpr int NIT = 48;   // 1536 / 32
    __shared__ __align__(16) __nv_bfloat16 As[2 * 128 * 40];
    __shared__ __align__(16) __nv_bfloat16 Bs[2 * 32 * 136];
    int b = blockIdx.z;
    int nbase = blockIdx.x * 128;
    int tid = threadIdx.x, lane = tid & 31, warp = tid >> 5;
    int wm = warp & 3, wn = warp >> 2;
    const __nv_bfloat16* xh = g_xbf + (long)b * CC * NN;
    const __nv_bfloat16* xl = g_xlo + (long)b * CC * NN;

    float acc[2][8][4];
#pragma unroll
    for (int t = 0; t < 2; t++)
#pragma unroll
        for (int j = 0; j < 8; j++)
#pragma unroll
            for (int e = 0; e < 4; e++) acc[t][j][e] = 0.f;

    uint32_t as0 = (uint32_t)__cvta_generic_to_shared(As);
    uint32_t bs0 = (uint32_t)__cvta_generic_to_shared(Bs);
    uint32_t a_st = ((tid >> 2) * 40 + (tid & 3) * 8) * 2;
    uint32_t b_st = ((tid >> 4) * 136 + (tid & 15) * 8) * 2;
    const long a_g0 = (long)(tid >> 2) * 1536 + (tid & 3) * 8;
    const long b_g0 = (long)(tid >> 4) * NN + nbase + (tid & 15) * 8;
    uint32_t a_off = ((wm * 32 + (lane & 15)) * 40 + (lane >> 4) * 8) * 2;
    uint32_t b_off = ((lane & 15) * 136 + wn * 64 + (lane >> 4) * 8) * 2;

    auto issue = [&](int c, int st) {
        uint32_t ab = as0 + st * 10240, bb = bs0 + st * 8704;
        cp16(ab + a_st, g_Wqk2 + a_g0 + c * 32);
        cp16(ab + a_st + 64 * 80, g_Wqk2 + a_g0 + 64L * 1536 + c * 32);
        const __nv_bfloat16* Bsrc =
            (c < 16) ? (xh + (long)(c * 32) * NN)
                     : (c < 32) ? (xh + (long)((c - 16) * 32) * NN)
                                : (xl + (long)((c - 32) * 32) * NN);
        cp16(bb + b_st, Bsrc + b_g0);
        cp16(bb + b_st + 16 * 272, Bsrc + b_g0 + 16L * NN);
        asm volatile("cp.async.commit_group;" ::);
    };

    issue(0, 0);
    for (int it = 0; it < NIT; it++) {
        if (it + 1 < NIT) {
            issue(it + 1, (it + 1) & 1);
            asm volatile("cp.async.wait_group 1;" ::);
        } else {
            asm volatile("cp.async.wait_group 0;" ::);
        }
        __syncthreads();
        uint32_t aa = as0 + (it & 1) * 10240 + a_off;
        uint32_t bb2 = bs0 + (it & 1) * 8704 + b_off;
#pragma unroll
        for (int ks = 0; ks < 2; ks++) {
            unsigned af[2][4];
            ldsm_x4(af[0], aa + ks * 32);
            ldsm_x4(af[1], aa + 1280 + ks * 32);
#pragma unroll
            for (int jp = 0; jp < 4; jp++) {
                unsigned bf[4];
                ldsm_x4t(bf, bb2 + jp * 32 + ks * 4352);
                mma_bf16(acc[0][2 * jp],     af[0], bf);
                mma_bf16(acc[0][2 * jp + 1], af[0], bf + 2);
                mma_bf16(acc[1][2 * jp],     af[1], bf);
                mma_bf16(acc[1][2 * jp + 1], af[1], bf + 2);
            }
        }
        __syncthreads();
    }

    int row0 = wm * 32 + (lane >> 2);
    int col0 = nbase + wn * 64 + (lane & 3) * 2;
#pragma unroll
    for (int t = 0; t < 2; t++)
#pragma unroll
        for (int rr = 0; rr < 2; rr++) {
            int d = row0 + t * 16 + rr * 8;
            float* dst = (d < 64) ? (g_q + ((long)b * DD + d) * NN)
                                  : (g_k + ((long)b * DD + d - 64) * NN);
#pragma unroll
            for (int j = 0; j < 8; j++) {
                float2 o = {acc[t][j][rr * 2], acc[t][j][rr * 2 + 1]};
                *(float2*)(dst + col0 + j * 8) = o;
            }
        }
}

// ---------------- split fp32 -> 3-term bf16 layouts --------------------------
// k2 rows: [0:64)=hk, [64:128)=hk, [128:192)=lk
__global__ void split_k_kernel() {
    long i = ((long)blockIdx.x * 256 + threadIdx.x) * 4;
    float4 v = *(const float4*)(g_k + i);
    float h0 = __bfloat162float(__float2bfloat16(v.x));
    float h1 = __bfloat162float(__float2bfloat16(v.y));
    float h2 = __bfloat162float(__float2bfloat16(v.z));
    float h3 = __bfloat162float(__float2bfloat16(v.w));
    long b = i / (64L * 4096);
    long r = i - b * (64L * 4096);
    __nv_bfloat16* dst = g_k2 + b * (192L * 4096);
    __nv_bfloat162 hA = __floats2bfloat162_rn(h0, h1);
    __nv_bfloat162 hBv = __floats2bfloat162_rn(h2, h3);
    *(__nv_bfloat162*)(dst + r)     = hA;
    *(__nv_bfloat162*)(dst + r + 2) = hBv;
    *(__nv_bfloat162*)(dst + 64L * 4096 + r)     = hA;
    *(__nv_bfloat162*)(dst + 64L * 4096 + r + 2) = hBv;
    *(__nv_bfloat162*)(dst + 128L * 4096 + r)     = __floats2bfloat162_rn(v.x - h0, v.y - h1);
    *(__nv_bfloat162*)(dst + 128L * 4096 + r + 2) = __floats2bfloat162_rn(v.z - h2, v.w - h3);
}

// q2t[b][n][0:64)=hq, [64:128)=lq, [128:192)=hq
__global__ __launch_bounds__(256) void split_q_kernel() {
    __shared__ __nv_bfloat16 shi[64 * 65];
    __shared__ __nv_bfloat16 slo[64 * 65];
    int b = blockIdx.y;
    int n0 = blockIdx.x * 64;
    int t = threadIdx.x;
    const float* src = g_q + (long)b * 64 * NN;
#pragma unroll
    for (int i = 0; i < 16; i++) {
        int idx = i * 256 + t;
        int d = idx >> 6, n = idx & 63;
        float v = src[(long)d * NN + n0 + n];
        __nv_bfloat16 h = __float2bfloat16(v);
        shi[d * 65 + n] = h;
        slo[d * 65 + n] = __float2bfloat16(v - __bfloat162float(h));
    }
    __syncthreads();
    __nv_bfloat16* dst = g_q2t + (long)b * NN * 192;
#pragma unroll
    for (int i = 0; i < 8; i++) {
        int idx = i * 256 + t;
        int n = idx >> 5, j = idx & 31;
        const __nv_bfloat16* sarr = (j < 16) ? shi : slo;
        int d0 = (j & 15) * 4;
        __nv_bfloat16 tmp[4];
#pragma unroll
        for (int r = 0; r < 4; r++) tmp[r] = sarr[(d0 + r) * 65 + n];
        int dc = (j < 16) ? d0 : (64 + d0);
        *(uint2*)(dst + (long)(n0 + n) * 192 + dc) = *(uint2*)tmp;
    }
    // duplicate hi block into cols [128,192)
#pragma unroll
    for (int i = 0; i < 4; i++) {
        int idx = i * 256 + t;
        int n = idx >> 4, j = idx & 15;
        int d0 = j * 4;
        __nv_bfloat16 tmp[4];
#pragma unroll
        for (int r = 0; r < 4; r++) tmp[r] = shi[(d0 + r) * 65 + n];
        *(uint2*)(dst + (long)(n0 + n) * 192 + 128 + d0) = *(uint2*)tmp;
    }
}

// ---------------- qk via 3-term bf16 GEMM (K=192) + exp + colpart ------------
__global__ __launch_bounds__(256, 2)
void qk_mma_kernel() {
    constexpr int KD = 192;
    constexpr int NIT = KD / 32;
    __shared__ __align__(16) __nv_bfloat16 As[2 * 128 * 40];
    __shared__ __align__(16) __nv_bfloat16 Bs[2 * 32 * 136];
    __shared__ float cred[4 * 128];
    int b = blockIdx.z;
    const __nv_bfloat16* A  = g_q2t + (long)b * NN * KD;
    const __nv_bfloat16* Bm = g_k2  + (long)b * KD * NN;
    int mbase = blockIdx.y * 128;
    int nbase = blockIdx.x * 128;
    int tid = threadIdx.x, lane = tid & 31, warp = tid >> 5;
    int wm = warp & 3, wn = warp >> 2;

    float acc[2][8][4];
#pragma unroll
    for (int t = 0; t < 2; t++)
#pragma unroll
        for (int j = 0; j < 8; j++)
#pragma unroll
            for (int e = 0; e < 4; e++) acc[t][j][e] = 0.f;

    uint32_t as0 = (uint32_t)__cvta_generic_to_shared(As);
    uint32_t bs0 = (uint32_t)__cvta_generic_to_shared(Bs);
    uint32_t a_st = ((tid >> 2) * 40 + (tid & 3) * 8) * 2;
    uint32_t b_st = ((tid >> 4) * 136 + (tid & 15) * 8) * 2;
    const long a_g0 = (long)(mbase + (tid >> 2)) * KD + (tid & 3) * 8;
    const long b_g0 = (long)(tid >> 4) * NN + nbase + (tid & 15) * 8;
    uint32_t a_off = ((wm * 32 + (lane & 15)) * 40 + (lane >> 4) * 8) * 2;
    uint32_t b_off = ((lane & 15) * 136 + wn * 64 + (lane >> 4) * 8) * 2;

#define QK_ISSUE(k0, st)                                                        \
    {                                                                           \
        uint32_t ab = as0 + (st) * 10240, bb = bs0 + (st) * 8704;               \
        cp16(ab + a_st, A + a_g0 + (k0));                                       \
        cp16(ab + a_st + 64 * 80, A + a_g0 + 64L * KD + (k0));                  \
        cp16(bb + b_st, Bm + b_g0 + (long)(k0) * NN);                           \
        cp16(bb + b_st + 16 * 272, Bm + b_g0 + (long)((k0) + 16) * NN);         \
        asm volatile("cp.async.commit_group;" ::);                              \
    }

    QK_ISSUE(0, 0);
#pragma unroll
    for (int it = 0; it < NIT; it++) {
        if (it + 1 < NIT) {
            QK_ISSUE((it + 1) * 32, (it + 1) & 1);
            asm volatile("cp.async.wait_group 1;" ::);
        } else {
            asm volatile("cp.async.wait_group 0;" ::);
        }
        __syncthreads();
        uint32_t aa = as0 + (it & 1) * 10240 + a_off;
        uint32_t bbq = bs0 + (it & 1) * 8704 + b_off;
#pragma unroll
        for (int ks = 0; ks < 2; ks++) {
            unsigned af[2][4];
            ldsm_x4(af[0], aa + ks * 32);
            ldsm_x4(af[1], aa + 1280 + ks * 32);
#pragma unroll
            for (int jp = 0; jp < 4; jp++) {
                unsigned bf[4];
                ldsm_x4t(bf, bbq + jp * 32 + ks * 4352);
                mma_bf16(acc[0][2 * jp],     af[0], bf);
                mma_bf16(acc[0][2 * jp + 1], af[0], bf + 2);
                mma_bf16(acc[1][2 * jp],     af[1], bf);
                mma_bf16(acc[1][2 * jp + 1], af[1], bf + 2);
            }
        }
        __syncthreads();
    }
#undef QK_ISSUE

    __nv_bfloat16* ab = g_attn + ((long)b << 24);
    int row0 = mbase + wm * 32 + (lane >> 2);
    int col0 = nbase + wn * 64 + (lane & 3) * 2;
    float colp[8][2];
#pragma unroll
    for (int j = 0; j < 8; j++) { colp[j][0] = 0.f; colp[j][1] = 0.f; }
#pragma unroll
    for (int t = 0; t < 2; t++)
#pragma unroll
        for (int j = 0; j < 8; j++) {
            float e0 = fast_exp(acc[t][j][0]);
            float e1 = fast_exp(acc[t][j][1]);
            float e2 = fast_exp(acc[t][j][2]);
            float e3 = fast_exp(acc[t][j][3]);
            colp[j][0] += e0 + e2;
            colp[j][1] += e1 + e3;
            int r = row0 + t * 16, c = col0 + j * 8;
            *(__nv_bfloat162*)(ab + (long)r * NN + c)       = __floats2bfloat162_rn(e0, e1);
            *(__nv_bfloat162*)(ab + (long)(r + 8) * NN + c) = __floats2bfloat162_rn(e2, e3);
        }
#pragma unroll
    for (int off = 16; off >= 4; off >>= 1)
#pragma unroll
        for (int j = 0; j < 8; j++) {
            colp[j][0] += __shfl_xor_sync(0xffffffffu, colp[j][0], off);
            colp[j][1] += __shfl_xor_sync(0xffffffffu, colp[j][1], off);
        }
    if ((lane >> 2) == 0) {
#pragma unroll
        for (int j = 0; j < 8; j++) {
            cred[wm * 128 + wn * 64 + j * 8 + (lane & 3) * 2]     = colp[j][0];
            cred[wm * 128 + wn * 64 + j * 8 + (lane & 3) * 2 + 1] = colp[j][1];
        }
    }
    __syncthreads();
    if (tid < 128) {
        float s = cred[tid] + cred[128 + tid] + cred[256 + tid] + cred[384 + tid];
        g_colpart[((long)b * 32 + blockIdx.y) * NN + nbase + tid] = s;
    }
}

// ---------------- column sum finalize ----------------------------------------
__global__ void rsum_kernel(const float* __restrict__ gamma) {
    int i = blockIdx.x * 256 + threadIdx.x;
    int b = i >> 12, col = i & 4095;
    const float* p = g_colpart + (long)b * 32 * NN + col;
    float s = 0.f;
#pragma unroll
    for (int t = 0; t < 32; t++) s += p[(long)t * NN];
    g_colsum[i] = gamma[0] / s;
}

// ---------------- bf16 tensor-core GEMM (v-proj and PV) ----------------------
template <int KDIM, bool PV>
__global__ __launch_bounds__(256, 2)
void mma_gemm_kernel(float* __restrict__ Out, const float* __restrict__ Xres) {
    constexpr int NIT = KDIM / 32;
    __shared__ __align__(16) __nv_bfloat16 As[2 * 128 * 40];
    __shared__ __align__(16) __nv_bfloat16 Bs[2 * 32 * 136];
    int b = blockIdx.z;
    const __nv_bfloat16* A  = PV ? (g_v + (long)b * CC * NN) : g_Wvbf;
    const __nv_bfloat16* Bm = PV ? (g_attn + ((long)b << 24)) : (g_xbf + (long)b * CC * NN);
    int mbase = blockIdx.y * 128, nbase = blockIdx.x * 128;
    int tid = threadIdx.x, lane = tid & 31, warp = tid >> 5;
    int wm = warp & 3, wn = warp >> 2;

    float acc[2][8][4];
#pragma unroll
    for (int t = 0; t < 2; t++)
#pragma unroll
        for (int j = 0; j < 8; j++)
#pragma unroll
            for (int e = 0; e < 4; e++) acc[t][j][e] = 0.f;

    uint32_t as0 = (uint32_t)__cvta_generic_to_shared(As);
    uint32_t bs0 = (uint32_t)__cvta_generic_to_shared(Bs);
    uint32_t a_st = ((tid >> 2) * 40 + (tid & 3) * 8) * 2;
    uint32_t b_st = ((tid >> 4) * 136 + (tid & 15) * 8) * 2;
    const long a_g0 = (long)(mbase + (tid >> 2)) * KDIM + (tid & 3) * 8;
    const long b_g0 = (long)(tid >> 4) * NN + nbase + (tid & 15) * 8;
    uint32_t a_off = ((wm * 32 + (lane & 15)) * 40 + (lane >> 4) * 8) * 2;
    uint32_t b_off = ((lane & 15) * 136 + wn * 64 + (lane >> 4) * 8) * 2;

#define GM_ISSUE(k0, st)                                                        \
    {                                                                           \
        uint32_t ab = as0 + (st) * 10240, bb = bs0 + (st) * 8704;               \
        cp16(ab + a_st, A + a_g0 + (k0));                                       \
        cp16(ab + a_st + 64 * 80, A + a_g0 + 64L * KDIM + (k0));                \
        cp16(bb + b_st, Bm + b_g0 + (long)(k0) * NN);                           \
        cp16(bb + b_st + 16 * 272, Bm + b_g0 + (long)((k0) + 16) * NN);         \
        asm volatile("cp.async.commit_group;" ::);                              \
    }

    GM_ISSUE(0, 0);
    for (int it = 0; it < NIT; it++) {
        if (it + 1 < NIT) {
            GM_ISSUE((it + 1) * 32, (it + 1) & 1);
            asm volatile("cp.async.wait_group 1;" ::);
        } else {
            asm volatile("cp.async.wait_group 0;" ::);
        }
        __syncthreads();
        uint32_t aa = as0 + (it & 1) * 10240 + a_off;
        uint32_t bb2 = bs0 + (it & 1) * 8704 + b_off;
#pragma unroll
        for (int ks = 0; ks < 2; ks++) {
            unsigned af[2][4];
            ldsm_x4(af[0], aa + ks * 32);
            ldsm_x4(af[1], aa + 1280 + ks * 32);
#pragma unroll
            for (int jp = 0; jp < 4; jp++) {
                unsigned bf[4];
                ldsm_x4t(bf, bb2 + jp * 32 + ks * 4352);
                mma_bf16(acc[0][2 * jp],     af[0], bf);
                mma_bf16(acc[0][2 * jp + 1], af[0], bf + 2);
                mma_bf16(acc[1][2 * jp],     af[1], bf);
                mma_bf16(acc[1][2 * jp + 1], af[1], bf + 2);
            }
        }
        __syncthreads();
    }
#undef GM_ISSUE

    int row0 = mbase + wm * 32 + (lane >> 2);
    int col0 = nbase + wn * 64 + (lane & 3) * 2;
    if (!PV) {
        __nv_bfloat16* Vb = g_v + (long)b * CC * NN;
#pragma unroll
        for (int t = 0; t < 2; t++)
#pragma unroll
            for (int j = 0; j < 8; j++) {
                int r = row0 + t * 16, c = col0 + j * 8;
                *(__nv_bfloat162*)(Vb + (long)r * NN + c) =
                    __floats2bfloat162_rn(acc[t][j][0], acc[t][j][1]);
                *(__nv_bfloat162*)(Vb + (long)(r + 8) * NN + c) =
                    __floats2bfloat162_rn(acc[t][j][2], acc[t][j][3]);
            }
    } else {
        float* Ob = Out + (long)b * CC * NN;
        const float* Xb = Xres + (long)b * CC * NN;
        const float* rs = g_colsum + b * NN;
#pragma unroll
        for (int j = 0; j < 8; j++) {
            int c = col0 + j * 8;
            float r0 = rs[c], r1 = rs[c + 1];
#pragma unroll
            for (int t = 0; t < 2; t++) {
                int r = row0 + t * 16;
                float2 x0 = *(const float2*)(Xb + (long)r * NN + c);
                float2 o0 = {fmaf(acc[t][j][0], r0, x0.x), fmaf(acc[t][j][1], r1, x0.y)};
                *(float2*)(Ob + (long)r * NN + c) = o0;
                float2 x1 = *(const float2*)(Xb + (long)(r + 8) * NN + c);
                float2 o1 = {fmaf(acc[t][j][2], r0, x1.x), fmaf(acc[t][j][3], r1, x1.y)};
                *(float2*)(Ob + (long)(r + 8) * NN + c) = o1;
            }
        }
    }
}

// ---------------- launch -----------------------------------------------------
extern "C" void kernel_launch(void* const* d_in, const int* in_sizes, int n_in,
                              void* d_out, int out_size) {
    const float* x     = (const float*)d_in[0];
    const float* Wq    = (const float*)d_in[1];
    const float* Wk    = (const float*)d_in[2];
    const float* Wv    = (const float*)d_in[3];
    const float* gamma = (const float*)d_in[4];
    float* out = (float*)d_out;

    cvt_x_kernel<<<16384, 256>>>(x);
    cvt_wv_kernel<<<256, 256>>>(Wv);
    cvt_wqk_kernel<<<256, 256>>>(Wq, Wk);
    qkproj_mma_kernel<<<dim3(32, 1, 8), 256>>>();
    split_k_kernel<<<2048, 256>>>();
    split_q_kernel<<<dim3(64, 8), 256>>>();
    qk_mma_kernel<<<dim3(32, 32, 8), 256>>>();
    rsum_kernel<<<128, 256>>>(gamma);
    mma_gemm_kernel<512, false><<<dim3(32, 4, 8), 256>>>(nullptr, nullptr);   // v-proj
    mma_gemm_kernel<4096, true><<<dim3(32, 4, 8), 256>>>(out, x);             // PV + epilogue
}

// round 7
// speedup vs baseline: 2.4192x; 1.0969x over previous
#include <cuda_runtime.h>
#include <cuda_bf16.h>
#include <cuda_fp16.h>
#include <cstdint>

#define BB 8
#define CC 512
#define NN 4096
#define DD 64

// ---------------- scratch ----------------------------------------------------
__device__ __nv_bfloat16 g_attn[(long)BB * NN * NN];     // 256 MB attn[n][m] = exp(qk)
__device__ __nv_bfloat16 g_xbf[(long)BB * CC * NN];      // x hi
__device__ __nv_bfloat16 g_xlo[(long)BB * CC * NN];      // x lo
__device__ __nv_bfloat16 g_v[(long)BB * CC * NN];
__device__ __nv_bfloat16 g_Wvbf[CC * CC];
__device__ __nv_bfloat16 g_Wqk2[128 * 1536];             // [d][hW|lW|hW]
__device__ float g_q[(long)BB * DD * NN];                // [b][d][n] fp32
__device__ float g_k[(long)BB * DD * NN];                // [b][d][n] fp32
__device__ __half g_qt16[(long)BB * NN * DD];            // 4 MB [b][n][d]
__device__ __half g_k16[(long)BB * DD * NN];             // 4 MB [b][d][m]
__device__ float g_colpart[(long)BB * 32 * NN];
__device__ float g_colsum[BB * NN];

// ---------------- helpers ----------------------------------------------------
__device__ __forceinline__ float fast_exp(float x) {
    float t = x * 1.4426950408889634f;
    float fi = floorf(t);
    float f = t - fi;
    float p = 1.5403530e-4f;
    p = fmaf(p, f, 1.3333558e-3f);
    p = fmaf(p, f, 9.6181291e-3f);
    p = fmaf(p, f, 5.5504109e-2f);
    p = fmaf(p, f, 2.4022651e-1f);
    p = fmaf(p, f, 6.9314718e-1f);
    p = fmaf(p, f, 1.0f);
    int ei = (int)fi;
    float sc = __int_as_float((ei + 127) << 23);
    return p * sc;
}
__device__ __forceinline__ void ldsm_x4(unsigned r[4], uint32_t a) {
    asm volatile("ldmatrix.sync.aligned.m8n8.x4.shared.b16 {%0,%1,%2,%3}, [%4];"
                 : "=r"(r[0]), "=r"(r[1]), "=r"(r[2]), "=r"(r[3]) : "r"(a));
}
__device__ __forceinline__ void ldsm_x4t(unsigned r[4], uint32_t a) {
    asm volatile("ldmatrix.sync.aligned.m8n8.x4.trans.shared.b16 {%0,%1,%2,%3}, [%4];"
                 : "=r"(r[0]), "=r"(r[1]), "=r"(r[2]), "=r"(r[3]) : "r"(a));
}
__device__ __forceinline__ void mma_bf16(float c[4], const unsigned a[4], const unsigned b2[2]) {
    asm volatile("mma.sync.aligned.m16n8k16.row.col.f32.bf16.bf16.f32 "
                 "{%0,%1,%2,%3},{%4,%5,%6,%7},{%8,%9},{%0,%1,%2,%3};"
                 : "+f"(c[0]), "+f"(c[1]), "+f"(c[2]), "+f"(c[3])
                 : "r"(a[0]), "r"(a[1]), "r"(a[2]), "r"(a[3]), "r"(b2[0]), "r"(b2[1]));
}
__device__ __forceinline__ void mma_f16(float c[4], const unsigned a[4], const unsigned b2[2]) {
    asm volatile("mma.sync.aligned.m16n8k16.row.col.f32.f16.f16.f32 "
                 "{%0,%1,%2,%3},{%4,%5,%6,%7},{%8,%9},{%0,%1,%2,%3};"
                 : "+f"(c[0]), "+f"(c[1]), "+f"(c[2]), "+f"(c[3])
                 : "r"(a[0]), "r"(a[1]), "r"(a[2]), "r"(a[3]), "r"(b2[0]), "r"(b2[1]));
}
__device__ __forceinline__ void cp16(uint32_t s, const void* g) {
    asm volatile("cp.async.cg.shared.global [%0], [%1], 16;" :: "r"(s), "l"(g));
}
__device__ __forceinline__ uint32_t smem_u32(const void* p) {
    return (uint32_t)__cvta_generic_to_shared(p);
}

// ---------------- converts ---------------------------------------------------
__global__ void cvt_x_kernel(const float* __restrict__ x) {
    long i = ((long)blockIdx.x * blockDim.x + threadIdx.x) * 4;
    float4 v = *(const float4*)(x + i);
    float h0 = __bfloat162float(__float2bfloat16(v.x));
    float h1 = __bfloat162float(__float2bfloat16(v.y));
    float h2 = __bfloat162float(__float2bfloat16(v.z));
    float h3 = __bfloat162float(__float2bfloat16(v.w));
    *(__nv_bfloat162*)(g_xbf + i)     = __floats2bfloat162_rn(h0, h1);
    *(__nv_bfloat162*)(g_xbf + i + 2) = __floats2bfloat162_rn(h2, h3);
    *(__nv_bfloat162*)(g_xlo + i)     = __floats2bfloat162_rn(v.x - h0, v.y - h1);
    *(__nv_bfloat162*)(g_xlo + i + 2) = __floats2bfloat162_rn(v.z - h2, v.w - h3);
}
__global__ void cvt_wv_kernel(const float* __restrict__ w) {
    long i = ((long)blockIdx.x * blockDim.x + threadIdx.x) * 4;
    float4 v = *(const float4*)(w + i);
    *(__nv_bfloat162*)(g_Wvbf + i)     = __floats2bfloat162_rn(v.x, v.y);
    *(__nv_bfloat162*)(g_Wvbf + i + 2) = __floats2bfloat162_rn(v.z, v.w);
}
__global__ void cvt_wqk_kernel(const float* __restrict__ Wq, const float* __restrict__ Wk) {
    int i = blockIdx.x * 256 + threadIdx.x;
    int d = i >> 9, c = i & 511;
    float v = (d < 64) ? Wq[d * 512 + c] : Wk[(d - 64) * 512 + c];
    __nv_bfloat16 h = __float2bfloat16(v);
    __nv_bfloat16 l = __float2bfloat16(v - __bfloat162float(h));
    g_Wqk2[d * 1536 + c] = h;
    g_Wqk2[d * 1536 + 512 + c] = l;
    g_Wqk2[d * 1536 + 1024 + c] = h;
}

// ---------------- qk projection (bf16 split GEMM K=1536) ---------------------
__global__ __launch_bounds__(256, 2)
void qkproj_mma_kernel() {
    constexpr int NIT = 48;
    __shared__ __align__(16) __nv_bfloat16 As[2 * 128 * 40];
    __shared__ __align__(16) __nv_bfloat16 Bs[2 * 32 * 136];
    int b = blockIdx.z;
    int nbase = blockIdx.x * 128;
    int tid = threadIdx.x, lane = tid & 31, warp = tid >> 5;
    int wm = warp & 3, wn = warp >> 2;
    const __nv_bfloat16* xh = g_xbf + (long)b * CC * NN;
    const __nv_bfloat16* xl = g_xlo + (long)b * CC * NN;

    float acc[2][8][4];
#pragma unroll
    for (int t = 0; t < 2; t++)
#pragma unroll
        for (int j = 0; j < 8; j++)
#pragma unroll
            for (int e = 0; e < 4; e++) acc[t][j][e] = 0.f;

    uint32_t as0 = smem_u32(As), bs0 = smem_u32(Bs);
    uint32_t a_st = ((tid >> 2) * 40 + (tid & 3) * 8) * 2;
    uint32_t b_st = ((tid >> 4) * 136 + (tid & 15) * 8) * 2;
    const long a_g0 = (long)(tid >> 2) * 1536 + (tid & 3) * 8;
    const long b_g0 = (long)(tid >> 4) * NN + nbase + (tid & 15) * 8;
    uint32_t a_off = ((wm * 32 + (lane & 15)) * 40 + (lane >> 4) * 8) * 2;
    uint32_t b_off = ((lane & 15) * 136 + wn * 64 + (lane >> 4) * 8) * 2;

    auto issue = [&](int c, int st) {
        uint32_t ab = as0 + st * 10240, bb = bs0 + st * 8704;
        cp16(ab + a_st, g_Wqk2 + a_g0 + c * 32);
        cp16(ab + a_st + 64 * 80, g_Wqk2 + a_g0 + 64L * 1536 + c * 32);
        const __nv_bfloat16* Bsrc =
            (c < 16) ? (xh + (long)(c * 32) * NN)
                     : (c < 32) ? (xh + (long)((c - 16) * 32) * NN)
                                : (xl + (long)((c - 32) * 32) * NN);
        cp16(bb + b_st, Bsrc + b_g0);
        cp16(bb + b_st + 16 * 272, Bsrc + b_g0 + 16L * NN);
        asm volatile("cp.async.commit_group;" ::);
    };

    issue(0, 0);
    for (int it = 0; it < NIT; it++) {
        if (it + 1 < NIT) {
            issue(it + 1, (it + 1) & 1);
            asm volatile("cp.async.wait_group 1;" ::);
        } else {
            asm volatile("cp.async.wait_group 0;" ::);
        }
        __syncthreads();
        uint32_t aa = as0 + (it & 1) * 10240 + a_off;
        uint32_t bb2 = bs0 + (it & 1) * 8704 + b_off;
#pragma unroll
        for (int ks = 0; ks < 2; ks++) {
            unsigned af[2][4];
            ldsm_x4(af[0], aa + ks * 32);
            ldsm_x4(af[1], aa + 1280 + ks * 32);
#pragma unroll
            for (int jp = 0; jp < 4; jp++) {
                unsigned bf[4];
                ldsm_x4t(bf, bb2 + jp * 32 + ks * 4352);
                mma_bf16(acc[0][2 * jp],     af[0], bf);
                mma_bf16(acc[0][2 * jp + 1], af[0], bf + 2);
                mma_bf16(acc[1][2 * jp],     af[1], bf);
                mma_bf16(acc[1][2 * jp + 1], af[1], bf + 2);
            }
        }
        __syncthreads();
    }

    int row0 = wm * 32 + (lane >> 2);
    int col0 = nbase + wn * 64 + (lane & 3) * 2;
#pragma unroll
    for (int t = 0; t < 2; t++)
#pragma unroll
        for (int rr = 0; rr < 2; rr++) {
            int d = row0 + t * 16 + rr * 8;
            float* dst = (d < 64) ? (g_q + ((long)b * DD + d) * NN)
                                  : (g_k + ((long)b * DD + d - 64) * NN);
#pragma unroll
            for (int j = 0; j < 8; j++) {
                float2 o = {acc[t][j][rr * 2], acc[t][j][rr * 2 + 1]};
                *(float2*)(dst + col0 + j * 8) = o;
            }
        }
}

// ---------------- fp16 converts for qk ---------------------------------------
__global__ void cvt_k16_kernel() {
    long i = ((long)blockIdx.x * 256 + threadIdx.x) * 4;
    float4 v = *(const float4*)(g_k + i);
    *(__half2*)(g_k16 + i)     = __floats2half2_rn(v.x, v.y);
    *(__half2*)(g_k16 + i + 2) = __floats2half2_rn(v.z, v.w);
}
__global__ __launch_bounds__(256) void cvt_qt_kernel() {
    __shared__ __half sh[64 * 65];
    int b = blockIdx.y;
    int n0 = blockIdx.x * 64;
    int t = threadIdx.x;
    const float* src = g_q + (long)b * 64 * NN;
#pragma unroll
    for (int i = 0; i < 16; i++) {
        int idx = i * 256 + t;
        int d = idx >> 6, n = idx & 63;
        sh[d * 65 + n] = __float2half(src[(long)d * NN + n0 + n]);
    }
    __syncthreads();
    __half* dst = g_qt16 + (long)b * NN * 64;
#pragma unroll
    for (int i = 0; i < 4; i++) {
        int idx = i * 256 + t;
        int n = idx >> 4, j = idx & 15;
        int d0 = j * 4;
        __half tmp[4];
#pragma unroll
        for (int r = 0; r < 4; r++) tmp[r] = sh[(d0 + r) * 65 + n];
        *(uint2*)(dst + (long)(n0 + n) * 64 + d0) = *(uint2*)tmp;
    }
}

// ---------------- qk fp16 GEMM (K=64) + exp + column partials ----------------
__global__ __launch_bounds__(256, 2)
void qk_mma_kernel() {
    constexpr int KD = 64;
    constexpr int NIT = KD / 32;
    __shared__ __align__(16) __half As[2 * 128 * 40];
    __shared__ __align__(16) __half Bs[2 * 32 * 136];
    __shared__ float cred[4 * 128];
    int b = blockIdx.z;
    const __half* A  = g_qt16 + (long)b * NN * KD;   // [n][64]
    const __half* Bm = g_k16  + (long)b * KD * NN;   // [d][m]
    int mbase = blockIdx.y * 128;  // n (softmax axis)
    int nbase = blockIdx.x * 128;  // m
    int tid = threadIdx.x, lane = tid & 31, warp = tid >> 5;
    int wm = warp & 3, wn = warp >> 2;

    float acc[2][8][4];
#pragma unroll
    for (int t = 0; t < 2; t++)
#pragma unroll
        for (int j = 0; j < 8; j++)
#pragma unroll
            for (int e = 0; e < 4; e++) acc[t][j][e] = 0.f;

    uint32_t as0 = smem_u32(As), bs0 = smem_u32(Bs);
    uint32_t a_st = ((tid >> 2) * 40 + (tid & 3) * 8) * 2;
    uint32_t b_st = ((tid >> 4) * 136 + (tid & 15) * 8) * 2;
    const long a_g0 = (long)(mbase + (tid >> 2)) * KD + (tid & 3) * 8;
    const long b_g0 = (long)(tid >> 4) * NN + nbase + (tid & 15) * 8;
    uint32_t a_off = ((wm * 32 + (lane & 15)) * 40 + (lane >> 4) * 8) * 2;
    uint32_t b_off = ((lane & 15) * 136 + wn * 64 + (lane >> 4) * 8) * 2;

#define QK_ISSUE(k0, st)                                                        \
    {                                                                           \
        uint32_t ab = as0 + (st) * 10240, bb = bs0 + (st) * 8704;               \
        cp16(ab + a_st, A + a_g0 + (k0));                                       \
        cp16(ab + a_st + 64 * 80, A + a_g0 + 64L * KD + (k0));                  \
        cp16(bb + b_st, Bm + b_g0 + (long)(k0) * NN);                           \
        cp16(bb + b_st + 16 * 272, Bm + b_g0 + (long)((k0) + 16) * NN);         \
        asm volatile("cp.async.commit_group;" ::);                              \
    }

    QK_ISSUE(0, 0);
#pragma unroll
    for (int it = 0; it < NIT; it++) {
        if (it + 1 < NIT) {
            QK_ISSUE((it + 1) * 32, (it + 1) & 1);
            asm volatile("cp.async.wait_group 1;" ::);
        } else {
            asm volatile("cp.async.wait_group 0;" ::);
        }
        __syncthreads();
        uint32_t aa = as0 + (it & 1) * 10240 + a_off;
        uint32_t bbq = bs0 + (it & 1) * 8704 + b_off;
#pragma unroll
        for (int ks = 0; ks < 2; ks++) {
            unsigned af[2][4];
            ldsm_x4(af[0], aa + ks * 32);
            ldsm_x4(af[1], aa + 1280 + ks * 32);
#pragma unroll
            for (int jp = 0; jp < 4; jp++) {
                unsigned bf[4];
                ldsm_x4t(bf, bbq + jp * 32 + ks * 4352);
                mma_f16(acc[0][2 * jp],     af[0], bf);
                mma_f16(acc[0][2 * jp + 1], af[0], bf + 2);
                mma_f16(acc[1][2 * jp],     af[1], bf);
                mma_f16(acc[1][2 * jp + 1], af[1], bf + 2);
            }
        }
        __syncthreads();
    }
#undef QK_ISSUE

    __nv_bfloat16* ab = g_attn + ((long)b << 24);
    int row0 = mbase + wm * 32 + (lane >> 2);
    int col0 = nbase + wn * 64 + (lane & 3) * 2;
    float colp[8][2];
#pragma unroll
    for (int j = 0; j < 8; j++) { colp[j][0] = 0.f; colp[j][1] = 0.f; }
#pragma unroll
    for (int t = 0; t < 2; t++)
#pragma unroll
        for (int j = 0; j < 8; j++) {
            float e0 = fast_exp(acc[t][j][0]);
            float e1 = fast_exp(acc[t][j][1]);
            float e2 = fast_exp(acc[t][j][2]);
            float e3 = fast_exp(acc[t][j][3]);
            colp[j][0] += e0 + e2;
            colp[j][1] += e1 + e3;
            int r = row0 + t * 16, c = col0 + j * 8;
            *(__nv_bfloat162*)(ab + (long)r * NN + c)       = __floats2bfloat162_rn(e0, e1);
            *(__nv_bfloat162*)(ab + (long)(r + 8) * NN + c) = __floats2bfloat162_rn(e2, e3);
        }
#pragma unroll
    for (int off = 16; off >= 4; off >>= 1)
#pragma unroll
        for (int j = 0; j < 8; j++) {
            colp[j][0] += __shfl_xor_sync(0xffffffffu, colp[j][0], off);
            colp[j][1] += __shfl_xor_sync(0xffffffffu, colp[j][1], off);
        }
    if ((lane >> 2) == 0) {
#pragma unroll
        for (int j = 0; j < 8; j++) {
            cred[wm * 128 + wn * 64 + j * 8 + (lane & 3) * 2]     = colp[j][0];
            cred[wm * 128 + wn * 64 + j * 8 + (lane & 3) * 2 + 1] = colp[j][1];
        }
    }
    __syncthreads();
    if (tid < 128) {
        float s = cred[tid] + cred[128 + tid] + cred[256 + tid] + cred[384 + tid];
        g_colpart[((long)b * 32 + blockIdx.y) * NN + nbase + tid] = s;
    }
}

// ---------------- column sum finalize ----------------------------------------
__global__ void rsum_kernel(const float* __restrict__ gamma) {
    int i = blockIdx.x * 256 + threadIdx.x;
    int b = i >> 12, col = i & 4095;
    const float* p = g_colpart + (long)b * 32 * NN + col;
    float s = 0.f;
#pragma unroll
    for (int t = 0; t < 32; t++) s += p[(long)t * NN];
    g_colsum[i] = gamma[0] / s;
}

// ---------------- bf16 tensor-core GEMM (v-proj and PV), 3-stage pipeline ----
template <int KDIM, bool PV>
__global__ __launch_bounds__(256)
void mma_gemm_kernel(float* __restrict__ Out, const float* __restrict__ Xres) {
    constexpr int NIT = KDIM / 32;
    extern __shared__ __align__(16) char dsm[];
    __nv_bfloat16* As = (__nv_bfloat16*)dsm;       // 3 * 5120 bf16
    __nv_bfloat16* Bs = As + 3 * 5120;             // 3 * 4352 bf16
    int b = blockIdx.z;
    const __nv_bfloat16* A  = PV ? (g_v + (long)b * CC * NN) : g_Wvbf;
    const __nv_bfloat16* Bm = PV ? (g_attn + ((long)b << 24)) : (g_xbf + (long)b * CC * NN);
    int mbase = blockIdx.y * 128, nbase = blockIdx.x * 128;
    int tid = threadIdx.x, lane = tid & 31, warp = tid >> 5;
    int wm = warp & 3, wn = warp >> 2;

    float acc[2][8][4];
#pragma unroll
    for (int t = 0; t < 2; t++)
#pragma unroll
        for (int j = 0; j < 8; j++)
#pragma unroll
            for (int e = 0; e < 4; e++) acc[t][j][e] = 0.f;

    uint32_t as0 = smem_u32(As), bs0 = smem_u32(Bs);
    uint32_t a_st = ((tid >> 2) * 40 + (tid & 3) * 8) * 2;
    uint32_t b_st = ((tid >> 4) * 136 + (tid & 15) * 8) * 2;
    const long a_g0 = (long)(mbase + (tid >> 2)) * KDIM + (tid & 3) * 8;
    const long b_g0 = (long)(tid >> 4) * NN + nbase + (tid & 15) * 8;
    uint32_t a_off = ((wm * 32 + (lane & 15)) * 40 + (lane >> 4) * 8) * 2;
    uint32_t b_off = ((lane & 15) * 136 + wn * 64 + (lane >> 4) * 8) * 2;

#define GM_ISSUE(k0, st)                                                        \
    {                                                                           \
        uint32_t ab = as0 + (st) * 10240, bb = bs0 + (st) * 8704;               \
        cp16(ab + a_st, A + a_g0 + (k0));                                       \
        cp16(ab + a_st + 64 * 80, A + a_g0 + 64L * KDIM + (k0));                \
        cp16(bb + b_st, Bm + b_g0 + (long)(k0) * NN);                           \
        cp16(bb + b_st + 16 * 272, Bm + b_g0 + (long)((k0) + 16) * NN);         \
        asm volatile("cp.async.commit_group;" ::);                              \
    }

    GM_ISSUE(0, 0);
    GM_ISSUE(32, 1);
    for (int it = 0; it < NIT; it++) {
        if (it + 2 < NIT) {
            GM_ISSUE((it + 2) * 32, (it + 2) % 3);
            asm volatile("cp.async.wait_group 2;" ::);
        } else if (it + 1 < NIT) {
            asm volatile("cp.async.wait_group 1;" ::);
        } else {
            asm volatile("cp.async.wait_group 0;" ::);
        }
        __syncthreads();
        int st = it % 3;
        uint32_t aa = as0 + st * 10240 + a_off;
        uint32_t bb2 = bs0 + st * 8704 + b_off;
#pragma unroll
        for (int ks = 0; ks < 2; ks++) {
            unsigned af[2][4];
            ldsm_x4(af[0], aa + ks * 32);
            ldsm_x4(af[1], aa + 1280 + ks * 32);
#pragma unroll
            for (int jp = 0; jp < 4; jp++) {
                unsigned bf[4];
                ldsm_x4t(bf, bb2 + jp * 32 + ks * 4352);
                mma_bf16(acc[0][2 * jp],     af[0], bf);
                mma_bf16(acc[0][2 * jp + 1], af[0], bf + 2);
                mma_bf16(acc[1][2 * jp],     af[1], bf);
                mma_bf16(acc[1][2 * jp + 1], af[1], bf + 2);
            }
        }
        __syncthreads();
    }
#undef GM_ISSUE

    int row0 = mbase + wm * 32 + (lane >> 2);
    int col0 = nbase + wn * 64 + (lane & 3) * 2;
    if (!PV) {
        __nv_bfloat16* Vb = g_v + (long)b * CC * NN;
#pragma unroll
        for (int t = 0; t < 2; t++)
#pragma unroll
            for (int j = 0; j < 8; j++) {
                int r = row0 + t * 16, c = col0 + j * 8;
                *(__nv_bfloat162*)(Vb + (long)r * NN + c) =
                    __floats2bfloat162_rn(acc[t][j][0], acc[t][j][1]);
                *(__nv_bfloat162*)(Vb + (long)(r + 8) * NN + c) =
                    __floats2bfloat162_rn(acc[t][j][2], acc[t][j][3]);
            }
    } else {
        float* Ob = Out + (long)b * CC * NN;
        const float* Xb = Xres + (long)b * CC * NN;
        const float* rs = g_colsum + b * NN;
#pragma unroll
        for (int j = 0; j < 8; j++) {
            int c = col0 + j * 8;
            float r0 = rs[c], r1 = rs[c + 1];
#pragma unroll
            for (int t = 0; t < 2; t++) {
                int r = row0 + t * 16;
                float2 x0 = *(const float2*)(Xb + (long)r * NN + c);
                float2 o0 = {fmaf(acc[t][j][0], r0, x0.x), fmaf(acc[t][j][1], r1, x0.y)};
                *(float2*)(Ob + (long)r * NN + c) = o0;
                float2 x1 = *(const float2*)(Xb + (long)(r + 8) * NN + c);
                float2 o1 = {fmaf(acc[t][j][2], r0, x1.x), fmaf(acc[t][j][3], r1, x1.y)};
                *(float2*)(Ob + (long)(r + 8) * NN + c) = o1;
            }
        }
    }
}

// ---------------- launch -----------------------------------------------------
extern "C" void kernel_launch(void* const* d_in, const int* in_sizes, int n_in,
                              void* d_out, int out_size) {
    const float* x     = (const float*)d_in[0];
    const float* Wq    = (const float*)d_in[1];
    const float* Wk    = (const float*)d_in[2];
    const float* Wv    = (const float*)d_in[3];
    const float* gamma = (const float*)d_in[4];
    float* out = (float*)d_out;

    const int GEMM_SMEM = 3 * (10240 + 8704);  // 56832 bytes
    cudaFuncSetAttribute(mma_gemm_kernel<512, false>,
                         cudaFuncAttributeMaxDynamicSharedMemorySize, GEMM_SMEM);
    cudaFuncSetAttribute(mma_gemm_kernel<4096, true>,
                         cudaFuncAttributeMaxDynamicSharedMemorySize, GEMM_SMEM);

    cvt_x_kernel<<<16384, 256>>>(x);
    cvt_wv_kernel<<<256, 256>>>(Wv);
    cvt_wqk_kernel<<<256, 256>>>(Wq, Wk);
    qkproj_mma_kernel<<<dim3(32, 1, 8), 256>>>();
    cvt_k16_kernel<<<2048, 256>>>();
    cvt_qt_kernel<<<dim3(64, 8), 256>>>();
    qk_mma_kernel<<<dim3(32, 32, 8), 256>>>();
    rsum_kernel<<<128, 256>>>(gamma);
    mma_gemm_kernel<512, false><<<dim3(32, 4, 8), 256, GEMM_SMEM>>>(nullptr, nullptr);
    mma_gemm_kernel<4096, true><<<dim3(32, 4, 8), 256, GEMM_SMEM>>>(out, x);
}